// round 1
// baseline (speedup 1.0000x reference)
#include <cuda_runtime.h>

#define CC 256
#define NB 4
#define HWP 1024
#define SS 16
#define KTOT 4096
#define LAYERS 3
#define EPSF 1e-5f

// scratch (no allocations allowed)
__device__ unsigned char g_state[NB * SS * CC];
__device__ float g_Weff[LAYERS * NB * CC * CC]; // [l][n][o][c], alpha-folded

__device__ __forceinline__ float msel(float v, unsigned int s) {
    return s == 2u ? v : (s == 1u ? fmaxf(v, 0.0f) : 0.0f);
}

// ---------------------------------------------------------------------------
// Kernel A: per-(n, slice i, column c) positivity state of adj
// state = 2 if all 16 rows of slice i have adj[r,c] > 0, 1 if any, 0 if none
// ---------------------------------------------------------------------------
__global__ void state_kernel(const float* __restrict__ adj) {
    int n = blockIdx.x;
    int c = threadIdx.x;
    const float* m = adj + (size_t)n * CC * CC + c;
#pragma unroll
    for (int i = 0; i < SS; i++) {
        bool anyp = false, allp = true;
#pragma unroll
        for (int r = 0; r < CC / SS; r++) {
            bool p = m[(size_t)(i * (CC / SS) + r) * CC] > 0.0f;
            anyp |= p;
            allp &= p;
        }
        g_state[(n * SS + i) * CC + c] = (unsigned char)(allp ? 2 : (anyp ? 1 : 0));
    }
}

// ---------------------------------------------------------------------------
// Kernel B: W_eff[l,n][o,c] = alpha[l,o] * sum_{i,a} cw[l,o,i*256+a] * sel(state[n,i,c], adj[n,a,c])
// GEMM M=256(o) x N=256(c) x K=4096, B generated on the fly (mss never materialized).
// Tile 64x64, Kc=16, 256 threads, 4x4 thread tile, register prefetch.
// ---------------------------------------------------------------------------
__global__ __launch_bounds__(256) void weff_kernel(
    const float* __restrict__ adj, const float* __restrict__ cw,
    const float* __restrict__ gamma, const float* __restrict__ var)
{
    __shared__ float As[64 * 17];  // [o][k], pad 17
    __shared__ float Bs[16 * 68];  // [k][c], pad 68

    int pair = blockIdx.z;               // l*4 + n
    int l = pair >> 2, n = pair & 3;
    int o0 = blockIdx.y << 6, c0 = blockIdx.x << 6;
    int tid = threadIdx.x;
    int tm = tid >> 4, tc = tid & 15;

    // loader lanes
    int la_o = tid >> 2;               // 0..63
    int la_k = (tid & 3) << 2;         // 0,4,8,12
    int lb_k = tid >> 4;               // 0..15
    int lb_c = (tid & 15) << 2;        // 0..60

    const float* Ag = cw + (size_t)l * CC * KTOT + (size_t)(o0 + la_o) * KTOT + la_k;
    const float* adjn = adj + (size_t)n * CC * CC;

    int asw = la_o * 17 + la_k;
    int bsw = lb_k * 68 + lb_c;

    float4 acc0 = {0, 0, 0, 0}, acc1 = {0, 0, 0, 0}, acc2 = {0, 0, 0, 0}, acc3 = {0, 0, 0, 0};

    // prefetch chunk 0
    float4 ar = *(const float4*)(Ag);
    float4 br = *(const float4*)(adjn + (size_t)lb_k * CC + c0 + lb_c);
    uchar4 sr = *(const uchar4*)(g_state + (n * SS + 0) * CC + c0 + lb_c);

    for (int kb = 0; kb < KTOT; kb += 16) {
        As[asw + 0] = ar.x; As[asw + 1] = ar.y; As[asw + 2] = ar.z; As[asw + 3] = ar.w;
        float4 bm;
        bm.x = msel(br.x, sr.x);
        bm.y = msel(br.y, sr.y);
        bm.z = msel(br.z, sr.z);
        bm.w = msel(br.w, sr.w);
        *(float4*)&Bs[bsw] = bm;
        __syncthreads();

        int kn = kb + 16;
        if (kn < KTOT) {
            ar = *(const float4*)(Ag + kn);
            int a = (kn & 255) + lb_k;      // chunk never crosses a 256 boundary
            int i = kn >> 8;
            br = *(const float4*)(adjn + (size_t)a * CC + c0 + lb_c);
            sr = *(const uchar4*)(g_state + (n * SS + i) * CC + c0 + lb_c);
        }

#pragma unroll
        for (int k = 0; k < 16; k++) {
            float a0 = As[(tm * 4 + 0) * 17 + k];
            float a1 = As[(tm * 4 + 1) * 17 + k];
            float a2 = As[(tm * 4 + 2) * 17 + k];
            float a3 = As[(tm * 4 + 3) * 17 + k];
            float4 b = *(const float4*)&Bs[k * 68 + (tc << 2)];
            acc0.x += a0 * b.x; acc0.y += a0 * b.y; acc0.z += a0 * b.z; acc0.w += a0 * b.w;
            acc1.x += a1 * b.x; acc1.y += a1 * b.y; acc1.z += a1 * b.z; acc1.w += a1 * b.w;
            acc2.x += a2 * b.x; acc2.y += a2 * b.y; acc2.z += a2 * b.z; acc2.w += a2 * b.w;
            acc3.x += a3 * b.x; acc3.y += a3 * b.y; acc3.z += a3 * b.z; acc3.w += a3 * b.w;
        }
        __syncthreads();
    }

    // epilogue: fold BN scale alpha into W_eff rows
    float* W = g_Weff + (size_t)pair * CC * CC;
#pragma unroll
    for (int j = 0; j < 4; j++) {
        int o = o0 + tm * 4 + j;
        float al = gamma[l * CC + o] * rsqrtf(var[l * CC + o] + EPSF);
        float4 a = (j == 0) ? acc0 : ((j == 1) ? acc1 : ((j == 2) ? acc2 : acc3));
        float4 v = make_float4(al * a.x, al * a.y, al * a.z, al * a.w);
        *(float4*)(W + (size_t)o * CC + c0 + (tc << 2)) = v;
    }
}

// ---------------------------------------------------------------------------
// Kernel C: out = relu(W_eff[l,n] @ x[n] + B0[l,o]);  M=256(o) x N=1024(p) x K=256(c)
// ---------------------------------------------------------------------------
__global__ __launch_bounds__(256) void layer_kernel(
    const float* __restrict__ x, float* __restrict__ out, int l,
    const float* __restrict__ gamma, const float* __restrict__ beta,
    const float* __restrict__ mean, const float* __restrict__ var,
    const float* __restrict__ convb)
{
    __shared__ float As[64 * 17];
    __shared__ float Bs[16 * 68];

    int n = blockIdx.z;
    int o0 = blockIdx.y << 6, p0 = blockIdx.x << 6;
    int tid = threadIdx.x;
    int tm = tid >> 4, tc = tid & 15;

    int la_o = tid >> 2;
    int la_k = (tid & 3) << 2;
    int lb_k = tid >> 4;
    int lb_p = (tid & 15) << 2;

    const float* Ag = g_Weff + (size_t)(l * NB + n) * CC * CC + (size_t)(o0 + la_o) * CC + la_k;
    const float* Bg = x + (size_t)n * CC * HWP + (size_t)lb_k * HWP + p0 + lb_p;

    int asw = la_o * 17 + la_k;
    int bsw = lb_k * 68 + lb_p;

    float4 acc0 = {0, 0, 0, 0}, acc1 = {0, 0, 0, 0}, acc2 = {0, 0, 0, 0}, acc3 = {0, 0, 0, 0};

    float4 ar = *(const float4*)Ag;
    float4 br = *(const float4*)Bg;

    for (int kb = 0; kb < CC; kb += 16) {
        As[asw + 0] = ar.x; As[asw + 1] = ar.y; As[asw + 2] = ar.z; As[asw + 3] = ar.w;
        *(float4*)&Bs[bsw] = br;
        __syncthreads();

        int kn = kb + 16;
        if (kn < CC) {
            ar = *(const float4*)(Ag + kn);
            br = *(const float4*)(Bg + (size_t)kn * HWP);
        }

#pragma unroll
        for (int k = 0; k < 16; k++) {
            float a0 = As[(tm * 4 + 0) * 17 + k];
            float a1 = As[(tm * 4 + 1) * 17 + k];
            float a2 = As[(tm * 4 + 2) * 17 + k];
            float a3 = As[(tm * 4 + 3) * 17 + k];
            float4 b = *(const float4*)&Bs[k * 68 + (tc << 2)];
            acc0.x += a0 * b.x; acc0.y += a0 * b.y; acc0.z += a0 * b.z; acc0.w += a0 * b.w;
            acc1.x += a1 * b.x; acc1.y += a1 * b.y; acc1.z += a1 * b.z; acc1.w += a1 * b.w;
            acc2.x += a2 * b.x; acc2.y += a2 * b.y; acc2.z += a2 * b.z; acc2.w += a2 * b.w;
            acc3.x += a3 * b.x; acc3.y += a3 * b.y; acc3.z += a3 * b.z; acc3.w += a3 * b.w;
        }
        __syncthreads();
    }

    // epilogue: + alpha*(conv_b - mean) + beta, relu   (alpha already folded into W_eff)
    float* on = out + (size_t)n * CC * HWP;
#pragma unroll
    for (int j = 0; j < 4; j++) {
        int o = o0 + tm * 4 + j;
        float al = gamma[l * CC + o] * rsqrtf(var[l * CC + o] + EPSF);
        float b0 = al * (convb[l * CC + o] - mean[l * CC + o]) + beta[l * CC + o];
        float4 a = (j == 0) ? acc0 : ((j == 1) ? acc1 : ((j == 2) ? acc2 : acc3));
        float4 v;
        v.x = fmaxf(a.x + b0, 0.0f);
        v.y = fmaxf(a.y + b0, 0.0f);
        v.z = fmaxf(a.z + b0, 0.0f);
        v.w = fmaxf(a.w + b0, 0.0f);
        *(float4*)(on + (size_t)o * HWP + p0 + (tc << 2)) = v;
    }
}

extern "C" void kernel_launch(void* const* d_in, const int* in_sizes, int n_in,
                              void* d_out, int out_size) {
    const float* feats = (const float*)d_in[0];
    const float* adj   = (const float*)d_in[1];
    const float* cw    = (const float*)d_in[2];
    const float* cb    = (const float*)d_in[3];
    const float* gamma = (const float*)d_in[4];
    const float* beta  = (const float*)d_in[5];
    const float* mean  = (const float*)d_in[6];
    const float* var   = (const float*)d_in[7];
    float* out = (float*)d_out;

    state_kernel<<<NB, CC>>>(adj);
    weff_kernel<<<dim3(4, 4, LAYERS * NB), 256>>>(adj, cw, gamma, var);

    const float* x = feats;
    for (int l = 0; l < LAYERS; l++) {
        float* yl = out + (size_t)l * NB * CC * HWP;
        layer_kernel<<<dim3(16, 4, NB), 256>>>(x, yl, l, gamma, beta, mean, var, cb);
        x = yl;
    }
}

// round 2
// speedup vs baseline: 2.8428x; 2.8428x over previous
#include <cuda_runtime.h>

#define CC 256
#define NB 4
#define HWP 1024
#define SS 16
#define KTOT 4096
#define LAYERS 3
#define EPSF 1e-5f

// scratch (no allocations allowed)
__device__ unsigned char g_state[NB * SS * CC];
__device__ float g_cwsum[LAYERS * CC * CC];              // [l][o][a] = sum_i cw[l][o][i*256+a]
__device__ float g_Weff[LAYERS * NB * CC * CC];          // [l][n][o][c], alpha-folded

// ---------------------------------------------------------------------------
// Kernel A: per-(n, slice i, column c) positivity state of adj
// ---------------------------------------------------------------------------
__global__ void state_kernel(const float* __restrict__ adj) {
    int n = blockIdx.x;
    int c = threadIdx.x;
    const float* m = adj + (size_t)n * CC * CC + c;
#pragma unroll
    for (int i = 0; i < SS; i++) {
        bool anyp = false, allp = true;
#pragma unroll
        for (int r = 0; r < CC / SS; r++) {
            bool p = m[(size_t)(i * (CC / SS) + r) * CC] > 0.0f;
            anyp |= p;
            allp &= p;
        }
        g_state[(n * SS + i) * CC + c] = (unsigned char)(allp ? 2 : (anyp ? 1 : 0));
    }
}

// ---------------------------------------------------------------------------
// Kernel B: cwsum[l][o][a] = sum_i cw[l][o][i*256 + a]
// ---------------------------------------------------------------------------
__global__ void cwsum_kernel(const float* __restrict__ cw) {
    int o = blockIdx.x;
    int l = blockIdx.y;
    int a = threadIdx.x;
    const float* p = cw + ((size_t)l * CC + o) * KTOT + a;
    float s = 0.0f;
#pragma unroll
    for (int i = 0; i < SS; i++) s += p[(size_t)i * CC];
    g_cwsum[((size_t)l * CC + o) * CC + a] = s;
}

// ---------------------------------------------------------------------------
// Kernel C: W_base[l,n][o,c] = alpha[l,o] * sum_a cwsum[l][o][a] * relu(adj[n][a][c])
// GEMM 256x256x256, batch 12. 64x64 tile, double-buffered smem.
// ---------------------------------------------------------------------------
__global__ __launch_bounds__(256) void wbase_kernel(
    const float* __restrict__ adj,
    const float* __restrict__ gamma, const float* __restrict__ var)
{
    __shared__ float As[2][64 * 17];
    __shared__ float Bs[2][16 * 68];

    int pair = blockIdx.z;               // l*4 + n
    int l = pair >> 2, n = pair & 3;
    int o0 = blockIdx.y << 6, c0 = blockIdx.x << 6;
    int tid = threadIdx.x;
    int tm = tid >> 4, tc = tid & 15;

    int la_o = tid >> 2;
    int la_k = (tid & 3) << 2;
    int lb_k = tid >> 4;
    int lb_c = (tid & 15) << 2;

    const float* Ag = g_cwsum + (size_t)l * CC * CC + (size_t)(o0 + la_o) * CC + la_k;
    const float* Bg = adj + (size_t)n * CC * CC + (size_t)lb_k * CC + c0 + lb_c;

    int asw = la_o * 17 + la_k;
    int bsw = lb_k * 68 + lb_c;

    float4 acc0 = {0,0,0,0}, acc1 = {0,0,0,0}, acc2 = {0,0,0,0}, acc3 = {0,0,0,0};

    float4 ar = *(const float4*)Ag;
    float4 br = *(const float4*)Bg;
    {
        As[0][asw+0]=ar.x; As[0][asw+1]=ar.y; As[0][asw+2]=ar.z; As[0][asw+3]=ar.w;
        float4 bm = make_float4(fmaxf(br.x,0.f), fmaxf(br.y,0.f), fmaxf(br.z,0.f), fmaxf(br.w,0.f));
        *(float4*)&Bs[0][bsw] = bm;
    }
    __syncthreads();

    int stg = 0;
    for (int kb = 0; kb < CC; kb += 16) {
        int kn = kb + 16;
        if (kn < CC) {
            ar = *(const float4*)(Ag + kn);
            br = *(const float4*)(Bg + (size_t)kn * CC);
        }
#pragma unroll
        for (int k = 0; k < 16; k++) {
            float a0 = As[stg][(tm*4+0)*17 + k];
            float a1 = As[stg][(tm*4+1)*17 + k];
            float a2 = As[stg][(tm*4+2)*17 + k];
            float a3 = As[stg][(tm*4+3)*17 + k];
            float4 b = *(const float4*)&Bs[stg][k*68 + (tc<<2)];
            acc0.x += a0*b.x; acc0.y += a0*b.y; acc0.z += a0*b.z; acc0.w += a0*b.w;
            acc1.x += a1*b.x; acc1.y += a1*b.y; acc1.z += a1*b.z; acc1.w += a1*b.w;
            acc2.x += a2*b.x; acc2.y += a2*b.y; acc2.z += a2*b.z; acc2.w += a2*b.w;
            acc3.x += a3*b.x; acc3.y += a3*b.y; acc3.z += a3*b.z; acc3.w += a3*b.w;
        }
        if (kn < CC) {
            int ns = stg ^ 1;
            As[ns][asw+0]=ar.x; As[ns][asw+1]=ar.y; As[ns][asw+2]=ar.z; As[ns][asw+3]=ar.w;
            float4 bm = make_float4(fmaxf(br.x,0.f), fmaxf(br.y,0.f), fmaxf(br.z,0.f), fmaxf(br.w,0.f));
            *(float4*)&Bs[ns][bsw] = bm;
            stg = ns;
        }
        __syncthreads();
    }

    float* W = g_Weff + (size_t)pair * CC * CC;
#pragma unroll
    for (int j = 0; j < 4; j++) {
        int o = o0 + tm * 4 + j;
        float al = gamma[l * CC + o] * rsqrtf(var[l * CC + o] + EPSF);
        float4 a = (j == 0) ? acc0 : ((j == 1) ? acc1 : ((j == 2) ? acc2 : acc3));
        float4 v = make_float4(al*a.x, al*a.y, al*a.z, al*a.w);
        *(float4*)(W + (size_t)o * CC + c0 + (tc << 2)) = v;
    }
}

// ---------------------------------------------------------------------------
// Kernel D: exact corrections for rare (i,c) with state != 1.
// grid (LAYERS, NB), 256 threads. Deterministic per-(l,n) serial processing.
//   s==2: W[l,n][o,c] += alpha * sum_a cw[l,o,i*256+a] * min(adj[n,a,c], 0)
//   s==0: W[l,n][o,c] -= alpha * sum_a cw[l,o,i*256+a] * relu(adj[n,a,c])
// ---------------------------------------------------------------------------
__global__ __launch_bounds__(256) void corr_kernel(
    const float* __restrict__ adj, const float* __restrict__ cw,
    const float* __restrict__ gamma, const float* __restrict__ var)
{
    int l = blockIdx.x, n = blockIdx.y;
    int tid = threadIdx.x;
    __shared__ unsigned int masks[8];
    __shared__ float v[CC];

    float alpha = gamma[l * CC + tid] * rsqrtf(var[l * CC + tid] + EPSF); // o = tid

    for (int i = 0; i < SS; i++) {
        unsigned char s = g_state[(n * SS + i) * CC + tid];
        unsigned int bal = __ballot_sync(0xffffffffu, s != (unsigned char)1);
        if ((tid & 31) == 0) masks[tid >> 5] = bal;
        __syncthreads();
        for (int w = 0; w < 8; w++) {
            unsigned int m = masks[w];
            while (m) {
                int b = __ffs(m) - 1; m &= m - 1;
                int c = w * 32 + b;
                unsigned char sc = g_state[(n * SS + i) * CC + c];
                float av = adj[((size_t)n * CC + tid) * CC + c]; // a = tid
                v[tid] = (sc == (unsigned char)2) ? fminf(av, 0.0f) : -fmaxf(av, 0.0f);
                __syncthreads();
                const float* cwrow = cw + ((size_t)l * CC + tid) * KTOT + (size_t)i * CC;
                float dot = 0.0f;
#pragma unroll 8
                for (int a = 0; a < CC; a++) dot += cwrow[a] * v[a];
                g_Weff[((size_t)(l * NB + n) * CC + tid) * CC + c] += alpha * dot;
                __syncthreads();
            }
        }
        __syncthreads();
    }
}

// ---------------------------------------------------------------------------
// Kernel E: out = relu(W_eff[l,n] @ x[n] + B0[l,o]);  256(o) x 1024(p) x 256(c)
// double-buffered smem
// ---------------------------------------------------------------------------
__global__ __launch_bounds__(256) void layer_kernel(
    const float* __restrict__ x, float* __restrict__ out, int l,
    const float* __restrict__ gamma, const float* __restrict__ beta,
    const float* __restrict__ mean, const float* __restrict__ var,
    const float* __restrict__ convb)
{
    __shared__ float As[2][64 * 17];
    __shared__ float Bs[2][16 * 68];

    int n = blockIdx.z;
    int o0 = blockIdx.y << 6, p0 = blockIdx.x << 6;
    int tid = threadIdx.x;
    int tm = tid >> 4, tc = tid & 15;

    int la_o = tid >> 2;
    int la_k = (tid & 3) << 2;
    int lb_k = tid >> 4;
    int lb_p = (tid & 15) << 2;

    const float* Ag = g_Weff + (size_t)(l * NB + n) * CC * CC + (size_t)(o0 + la_o) * CC + la_k;
    const float* Bg = x + (size_t)n * CC * HWP + (size_t)lb_k * HWP + p0 + lb_p;

    int asw = la_o * 17 + la_k;
    int bsw = lb_k * 68 + lb_p;

    float4 acc0 = {0,0,0,0}, acc1 = {0,0,0,0}, acc2 = {0,0,0,0}, acc3 = {0,0,0,0};

    float4 ar = *(const float4*)Ag;
    float4 br = *(const float4*)Bg;
    {
        As[0][asw+0]=ar.x; As[0][asw+1]=ar.y; As[0][asw+2]=ar.z; As[0][asw+3]=ar.w;
        *(float4*)&Bs[0][bsw] = br;
    }
    __syncthreads();

    int stg = 0;
    for (int kb = 0; kb < CC; kb += 16) {
        int kn = kb + 16;
        if (kn < CC) {
            ar = *(const float4*)(Ag + kn);
            br = *(const float4*)(Bg + (size_t)kn * HWP);
        }
#pragma unroll
        for (int k = 0; k < 16; k++) {
            float a0 = As[stg][(tm*4+0)*17 + k];
            float a1 = As[stg][(tm*4+1)*17 + k];
            float a2 = As[stg][(tm*4+2)*17 + k];
            float a3 = As[stg][(tm*4+3)*17 + k];
            float4 b = *(const float4*)&Bs[stg][k*68 + (tc<<2)];
            acc0.x += a0*b.x; acc0.y += a0*b.y; acc0.z += a0*b.z; acc0.w += a0*b.w;
            acc1.x += a1*b.x; acc1.y += a1*b.y; acc1.z += a1*b.z; acc1.w += a1*b.w;
            acc2.x += a2*b.x; acc2.y += a2*b.y; acc2.z += a2*b.z; acc2.w += a2*b.w;
            acc3.x += a3*b.x; acc3.y += a3*b.y; acc3.z += a3*b.z; acc3.w += a3*b.w;
        }
        if (kn < CC) {
            int ns = stg ^ 1;
            As[ns][asw+0]=ar.x; As[ns][asw+1]=ar.y; As[ns][asw+2]=ar.z; As[ns][asw+3]=ar.w;
            *(float4*)&Bs[ns][bsw] = br;
            stg = ns;
        }
        __syncthreads();
    }

    float* on = out + (size_t)n * CC * HWP;
#pragma unroll
    for (int j = 0; j < 4; j++) {
        int o = o0 + tm * 4 + j;
        float al = gamma[l * CC + o] * rsqrtf(var[l * CC + o] + EPSF);
        float b0 = al * (convb[l * CC + o] - mean[l * CC + o]) + beta[l * CC + o];
        float4 a = (j == 0) ? acc0 : ((j == 1) ? acc1 : ((j == 2) ? acc2 : acc3));
        float4 v;
        v.x = fmaxf(a.x + b0, 0.0f);
        v.y = fmaxf(a.y + b0, 0.0f);
        v.z = fmaxf(a.z + b0, 0.0f);
        v.w = fmaxf(a.w + b0, 0.0f);
        *(float4*)(on + (size_t)o * HWP + p0 + (tc << 2)) = v;
    }
}

extern "C" void kernel_launch(void* const* d_in, const int* in_sizes, int n_in,
                              void* d_out, int out_size) {
    const float* feats = (const float*)d_in[0];
    const float* adj   = (const float*)d_in[1];
    const float* cw    = (const float*)d_in[2];
    const float* cb    = (const float*)d_in[3];
    const float* gamma = (const float*)d_in[4];
    const float* beta  = (const float*)d_in[5];
    const float* mean  = (const float*)d_in[6];
    const float* var   = (const float*)d_in[7];
    float* out = (float*)d_out;

    state_kernel<<<NB, CC>>>(adj);
    cwsum_kernel<<<dim3(CC, LAYERS), CC>>>(cw);
    wbase_kernel<<<dim3(4, 4, LAYERS * NB), 256>>>(adj, gamma, var);
    corr_kernel<<<dim3(LAYERS, NB), 256>>>(adj, cw, gamma, var);

    const float* x = feats;
    for (int l = 0; l < LAYERS; l++) {
        float* yl = out + (size_t)l * NB * CC * HWP;
        layer_kernel<<<dim3(16, 4, NB), 256>>>(x, yl, l, gamma, beta, mean, var, cb);
        x = yl;
    }
}

// round 3
// speedup vs baseline: 3.4198x; 1.2030x over previous
#include <cuda_runtime.h>

#define CC 256
#define NB 4
#define HWP 1024
#define SS 16
#define KTOT 4096
#define LAYERS 3
#define EPSF 1e-5f
#define MAXC 4096

// scratch (no allocations allowed)
__device__ int g_ncorr[NB];
__device__ int g_corr[NB * MAXC];                 // packed: c | i<<8 | s<<16
__device__ float g_cwsum[LAYERS * CC * CC];       // [l][o][a] = sum_i cw[l][o][i*256+a]
__device__ float g_Weff[LAYERS * NB * CC * CC];   // [l][n][o][c], alpha-folded

// ---------------------------------------------------------------------------
// Kernel A: positivity state + compact deterministic correction list per n.
// ---------------------------------------------------------------------------
__global__ void state_kernel(const float* __restrict__ adj) {
    int n = blockIdx.x;
    int c = threadIdx.x;                 // 256 threads, c = column
    int lane = c & 31, wid = c >> 5;
    __shared__ int warpcnt[8];
    __shared__ int cnt_s;
    if (c == 0) cnt_s = 0;
    __syncthreads();

    const float* m = adj + (size_t)n * CC * CC + c;
#pragma unroll
    for (int i = 0; i < SS; i++) {
        bool anyp = false, allp = true;
#pragma unroll
        for (int r = 0; r < CC / SS; r++) {
            bool p = m[(size_t)(i * (CC / SS) + r) * CC] > 0.0f;
            anyp |= p;
            allp &= p;
        }
        int s = allp ? 2 : (anyp ? 1 : 0);
        bool flag = (s != 1);
        unsigned int bal = __ballot_sync(0xffffffffu, flag);
        if (lane == 0) warpcnt[wid] = __popc(bal);
        __syncthreads();
        int pre = 0, tot = 0;
#pragma unroll
        for (int w = 0; w < 8; w++) {
            int v = warpcnt[w];
            if (w < wid) pre += v;
            tot += v;
        }
        if (flag) {
            int pos = cnt_s + pre + __popc(bal & ((1u << lane) - 1u));
            g_corr[n * MAXC + pos] = c | (i << 8) | (s << 16);
        }
        __syncthreads();
        if (c == 0) cnt_s += tot;
        __syncthreads();
    }
    if (c == 0) g_ncorr[n] = cnt_s;
}

// ---------------------------------------------------------------------------
// Kernel B: cwsum[l][o][a] = sum_i cw[l][o][i*256 + a]
// ---------------------------------------------------------------------------
__global__ void cwsum_kernel(const float* __restrict__ cw) {
    int o = blockIdx.x;
    int l = blockIdx.y;
    int a = threadIdx.x;
    const float* p = cw + ((size_t)l * CC + o) * KTOT + a;
    float s = 0.0f;
#pragma unroll
    for (int i = 0; i < SS; i++) s += p[(size_t)i * CC];
    g_cwsum[((size_t)l * CC + o) * CC + a] = s;
}

// ---------------------------------------------------------------------------
// Kernel C: W_base[l,n][o,c] = alpha[l,o] * sum_a cwsum[l][o][a] * relu(adj[n][a][c])
// GEMM 256x256x256, batch 12. 64x64 tile, double-buffered smem.
// ---------------------------------------------------------------------------
__global__ __launch_bounds__(256) void wbase_kernel(
    const float* __restrict__ adj,
    const float* __restrict__ gamma, const float* __restrict__ var)
{
    __shared__ float As[2][64 * 17];
    __shared__ float Bs[2][16 * 68];

    int pair = blockIdx.z;               // l*4 + n
    int l = pair >> 2, n = pair & 3;
    int o0 = blockIdx.y << 6, c0 = blockIdx.x << 6;
    int tid = threadIdx.x;
    int tm = tid >> 4, tc = tid & 15;

    int la_o = tid >> 2;
    int la_k = (tid & 3) << 2;
    int lb_k = tid >> 4;
    int lb_c = (tid & 15) << 2;

    const float* Ag = g_cwsum + (size_t)l * CC * CC + (size_t)(o0 + la_o) * CC + la_k;
    const float* Bg = adj + (size_t)n * CC * CC + (size_t)lb_k * CC + c0 + lb_c;

    int asw = la_o * 17 + la_k;
    int bsw = lb_k * 68 + lb_c;

    float4 acc0 = {0,0,0,0}, acc1 = {0,0,0,0}, acc2 = {0,0,0,0}, acc3 = {0,0,0,0};

    float4 ar = *(const float4*)Ag;
    float4 br = *(const float4*)Bg;
    {
        As[0][asw+0]=ar.x; As[0][asw+1]=ar.y; As[0][asw+2]=ar.z; As[0][asw+3]=ar.w;
        float4 bm = make_float4(fmaxf(br.x,0.f), fmaxf(br.y,0.f), fmaxf(br.z,0.f), fmaxf(br.w,0.f));
        *(float4*)&Bs[0][bsw] = bm;
    }
    __syncthreads();

    int stg = 0;
    for (int kb = 0; kb < CC; kb += 16) {
        int kn = kb + 16;
        if (kn < CC) {
            ar = *(const float4*)(Ag + kn);
            br = *(const float4*)(Bg + (size_t)kn * CC);
        }
#pragma unroll
        for (int k = 0; k < 16; k++) {
            float a0 = As[stg][(tm*4+0)*17 + k];
            float a1 = As[stg][(tm*4+1)*17 + k];
            float a2 = As[stg][(tm*4+2)*17 + k];
            float a3 = As[stg][(tm*4+3)*17 + k];
            float4 b = *(const float4*)&Bs[stg][k*68 + (tc<<2)];
            acc0.x += a0*b.x; acc0.y += a0*b.y; acc0.z += a0*b.z; acc0.w += a0*b.w;
            acc1.x += a1*b.x; acc1.y += a1*b.y; acc1.z += a1*b.z; acc1.w += a1*b.w;
            acc2.x += a2*b.x; acc2.y += a2*b.y; acc2.z += a2*b.z; acc2.w += a2*b.w;
            acc3.x += a3*b.x; acc3.y += a3*b.y; acc3.z += a3*b.z; acc3.w += a3*b.w;
        }
        if (kn < CC) {
            int ns = stg ^ 1;
            As[ns][asw+0]=ar.x; As[ns][asw+1]=ar.y; As[ns][asw+2]=ar.z; As[ns][asw+3]=ar.w;
            float4 bm = make_float4(fmaxf(br.x,0.f), fmaxf(br.y,0.f), fmaxf(br.z,0.f), fmaxf(br.w,0.f));
            *(float4*)&Bs[ns][bsw] = bm;
            stg = ns;
        }
        __syncthreads();
    }

    float* W = g_Weff + (size_t)pair * CC * CC;
#pragma unroll
    for (int j = 0; j < 4; j++) {
        int o = o0 + tm * 4 + j;
        float al = gamma[l * CC + o] * rsqrtf(var[l * CC + o] + EPSF);
        float4 a = (j == 0) ? acc0 : ((j == 1) ? acc1 : ((j == 2) ? acc2 : acc3));
        float4 v = make_float4(al*a.x, al*a.y, al*a.z, al*a.w);
        *(float4*)(W + (size_t)o * CC + c0 + (tc << 2)) = v;
    }
}

// ---------------------------------------------------------------------------
// Kernel D: exact corrections from compact list. Early-exit if none.
// Per correction (i,c,s): W[l,n][o,c] += alpha[o] * dot(cw[l,o,i,:], v[:])
//   v[a] = (s==2) ? min(adj[n,a,c],0) : -relu(adj[n,a,c])
// Warp-parallel matvec: lanes span 'a' (coalesced), shuffle reduce per o.
// ---------------------------------------------------------------------------
__global__ __launch_bounds__(256) void corr_kernel(
    const float* __restrict__ adj, const float* __restrict__ cw,
    const float* __restrict__ gamma, const float* __restrict__ var)
{
    int l = blockIdx.x, n = blockIdx.y;
    int cnt = g_ncorr[n];
    if (cnt == 0) return;

    int tid = threadIdx.x;
    int lane = tid & 31, wid = tid >> 5;
    __shared__ float v[CC];

    for (int e = 0; e < cnt; e++) {
        int ent = g_corr[n * MAXC + e];
        int c = ent & 255;
        int i = (ent >> 8) & 255;
        int s = ent >> 16;

        float av = adj[((size_t)n * CC + tid) * CC + c];   // a = tid (column gather)
        v[tid] = (s == 2) ? fminf(av, 0.0f) : -fmaxf(av, 0.0f);
        __syncthreads();

        // each warp handles 32 o's; lanes parallel over a
#pragma unroll 1
        for (int oo = 0; oo < 32; oo++) {
            int o = wid * 32 + oo;
            const float* row = cw + ((size_t)l * CC + o) * KTOT + (size_t)i * CC;
            float d = 0.0f;
#pragma unroll
            for (int j = 0; j < 8; j++) {
                int a = lane + 32 * j;
                d += row[a] * v[a];
            }
#pragma unroll
            for (int off = 16; off > 0; off >>= 1)
                d += __shfl_down_sync(0xffffffffu, d, off);
            if (lane == 0) {
                float al = gamma[l * CC + o] * rsqrtf(var[l * CC + o] + EPSF);
                g_Weff[(((size_t)(l * NB + n)) * CC + o) * CC + c] += al * d;
            }
        }
        __syncthreads();
    }
}

// ---------------------------------------------------------------------------
// Kernel E: out = relu(W_eff[l,n] @ x[n] + B0[l,o]); 256(o) x 1024(p) x 256(k)
// Tile 128x64, 8x4 microtile, A transposed in smem [k][o], double-buffered.
// Grid: (16 p-tiles, 2 o-tiles, 4 n) = 128 CTAs -> one clean wave.
// ---------------------------------------------------------------------------
__global__ __launch_bounds__(256) void layer_kernel(
    const float* __restrict__ x, float* __restrict__ out, int l,
    const float* __restrict__ gamma, const float* __restrict__ beta,
    const float* __restrict__ mean, const float* __restrict__ var,
    const float* __restrict__ convb)
{
    __shared__ float As[2][16 * 132];   // [k][o], row pad 132 (16B aligned)
    __shared__ float Bs[2][16 * 68];    // [k][p]

    int n = blockIdx.z;
    int o0 = blockIdx.y << 7, p0 = blockIdx.x << 6;
    int tid = threadIdx.x;
    int tm = tid >> 4, tc = tid & 15;   // tm: 0..15 -> 8 o rows; tc: 0..15 -> 4 p cols

    int la_o = tid >> 1;                // 0..127
    int la_k = (tid & 1) << 3;          // 0 or 8
    int lb_k = tid >> 4;                // 0..15
    int lb_p = (tid & 15) << 2;         // 0..60

    const float* Ag = g_Weff + (size_t)(l * NB + n) * CC * CC + (size_t)(o0 + la_o) * CC + la_k;
    const float* Bg = x + (size_t)n * CC * HWP + (size_t)lb_k * HWP + p0 + lb_p;

    float4 acc[8];
#pragma unroll
    for (int r = 0; r < 8; r++) acc[r] = make_float4(0.f, 0.f, 0.f, 0.f);

    float4 ar0 = *(const float4*)Ag;
    float4 ar1 = *(const float4*)(Ag + 4);
    float4 br  = *(const float4*)Bg;
    {
        As[0][(la_k+0)*132 + la_o] = ar0.x;
        As[0][(la_k+1)*132 + la_o] = ar0.y;
        As[0][(la_k+2)*132 + la_o] = ar0.z;
        As[0][(la_k+3)*132 + la_o] = ar0.w;
        As[0][(la_k+4)*132 + la_o] = ar1.x;
        As[0][(la_k+5)*132 + la_o] = ar1.y;
        As[0][(la_k+6)*132 + la_o] = ar1.z;
        As[0][(la_k+7)*132 + la_o] = ar1.w;
        *(float4*)&Bs[0][lb_k * 68 + lb_p] = br;
    }
    __syncthreads();

    int stg = 0;
    for (int kb = 0; kb < CC; kb += 16) {
        int kn = kb + 16;
        if (kn < CC) {
            ar0 = *(const float4*)(Ag + kn);
            ar1 = *(const float4*)(Ag + kn + 4);
            br  = *(const float4*)(Bg + (size_t)kn * HWP);
        }
#pragma unroll
        for (int k = 0; k < 16; k++) {
            float4 a0 = *(const float4*)&As[stg][k * 132 + tm * 8];
            float4 a1 = *(const float4*)&As[stg][k * 132 + tm * 8 + 4];
            float4 b  = *(const float4*)&Bs[stg][k * 68 + (tc << 2)];
            acc[0].x += a0.x*b.x; acc[0].y += a0.x*b.y; acc[0].z += a0.x*b.z; acc[0].w += a0.x*b.w;
            acc[1].x += a0.y*b.x; acc[1].y += a0.y*b.y; acc[1].z += a0.y*b.z; acc[1].w += a0.y*b.w;
            acc[2].x += a0.z*b.x; acc[2].y += a0.z*b.y; acc[2].z += a0.z*b.z; acc[2].w += a0.z*b.w;
            acc[3].x += a0.w*b.x; acc[3].y += a0.w*b.y; acc[3].z += a0.w*b.z; acc[3].w += a0.w*b.w;
            acc[4].x += a1.x*b.x; acc[4].y += a1.x*b.y; acc[4].z += a1.x*b.z; acc[4].w += a1.x*b.w;
            acc[5].x += a1.y*b.x; acc[5].y += a1.y*b.y; acc[5].z += a1.y*b.z; acc[5].w += a1.y*b.w;
            acc[6].x += a1.z*b.x; acc[6].y += a1.z*b.y; acc[6].z += a1.z*b.z; acc[6].w += a1.z*b.w;
            acc[7].x += a1.w*b.x; acc[7].y += a1.w*b.y; acc[7].z += a1.w*b.z; acc[7].w += a1.w*b.w;
        }
        if (kn < CC) {
            int ns = stg ^ 1;
            As[ns][(la_k+0)*132 + la_o] = ar0.x;
            As[ns][(la_k+1)*132 + la_o] = ar0.y;
            As[ns][(la_k+2)*132 + la_o] = ar0.z;
            As[ns][(la_k+3)*132 + la_o] = ar0.w;
            As[ns][(la_k+4)*132 + la_o] = ar1.x;
            As[ns][(la_k+5)*132 + la_o] = ar1.y;
            As[ns][(la_k+6)*132 + la_o] = ar1.z;
            As[ns][(la_k+7)*132 + la_o] = ar1.w;
            *(float4*)&Bs[ns][lb_k * 68 + lb_p] = br;
            stg = ns;
        }
        __syncthreads();
    }

    float* on = out + (size_t)n * CC * HWP;
#pragma unroll
    for (int r = 0; r < 8; r++) {
        int o = o0 + tm * 8 + r;
        float al = gamma[l * CC + o] * rsqrtf(var[l * CC + o] + EPSF);
        float b0 = al * (convb[l * CC + o] - mean[l * CC + o]) + beta[l * CC + o];
        float4 a = acc[r];
        float4 vv;
        vv.x = fmaxf(a.x + b0, 0.0f);
        vv.y = fmaxf(a.y + b0, 0.0f);
        vv.z = fmaxf(a.z + b0, 0.0f);
        vv.w = fmaxf(a.w + b0, 0.0f);
        *(float4*)(on + (size_t)o * HWP + p0 + (tc << 2)) = vv;
    }
}

extern "C" void kernel_launch(void* const* d_in, const int* in_sizes, int n_in,
                              void* d_out, int out_size) {
    const float* feats = (const float*)d_in[0];
    const float* adj   = (const float*)d_in[1];
    const float* cw    = (const float*)d_in[2];
    const float* cb    = (const float*)d_in[3];
    const float* gamma = (const float*)d_in[4];
    const float* beta  = (const float*)d_in[5];
    const float* mean  = (const float*)d_in[6];
    const float* var   = (const float*)d_in[7];
    float* out = (float*)d_out;

    state_kernel<<<NB, CC>>>(adj);
    cwsum_kernel<<<dim3(CC, LAYERS), CC>>>(cw);
    wbase_kernel<<<dim3(4, 4, LAYERS * NB), 256>>>(adj, gamma, var);
    corr_kernel<<<dim3(LAYERS, NB), 256>>>(adj, cw, gamma, var);

    const float* x = feats;
    for (int l = 0; l < LAYERS; l++) {
        float* yl = out + (size_t)l * NB * CC * HWP;
        layer_kernel<<<dim3(16, 2, NB), 256>>>(x, yl, l, gamma, beta, mean, var, cb);
        x = yl;
    }
}